// round 13
// baseline (speedup 1.0000x reference)
#include <cuda_runtime.h>
#include <cuda.h>
#include <cstdint>

// FWHT n=1024 over x[64,1024,512] f32, single pass, TMA-pipelined.
//
// R13: two independent pipelines per SM (2 CTAs/SM, 128 threads each,
// 8-float d-tiles = 32KB, 3 x 32KB buffers per CTA, depth-2 TMA prefetch,
// register FWHT, STG.64 output). Independent barrier domains drift into
// anti-phase, overlapping one CTA's memory phases with the other's
// butterflies. Transpose swizzle generalized to b ^ (a&3) for the
// narrower (4 x float2) lane layout; all smem accesses conflict-free.
//
// n = 32*a + b. Phase A: FWHT_32 over a (rows 32a+jt); swizzled smem
// exchange; Phase B: FWHT_32 over b (rows jt*32+b) -> STG.

#define FW_N 1024
#define FW_D 512
#define FW_TW 8                           // tile width in floats (32 B)
#define FW_THREADS 128
#define FW_NTILES (64 * (FW_D / FW_TW))   // 4096
#define FW_TILE_BYTES (FW_N * FW_TW * 4)  // 32768
#define FW_BOX_BYTES (FW_TILE_BYTES / 4)  // 8192 (256 rows per box)
#define FW_NBUF 3
#define FW_MBAR_OFF (FW_NBUF * FW_TILE_BYTES)
#define FW_SMEM_BYTES (FW_MBAR_OFF + 64)  // 98368 -> 2 CTAs/SM

typedef unsigned long long u64t;

// packed butterfly on a float2-as-u64: (a,b) -> (a+b, a-b)
__device__ __forceinline__ void bfly(u64t& a, u64t& b) {
    u64t s, d;
    asm("add.rn.f32x2 %0, %2, %3;\n\t"
        "sub.rn.f32x2 %1, %2, %3;"
        : "=l"(s), "=l"(d)
        : "l"(a), "l"(b));
    a = s; b = d;
}

__device__ __forceinline__ void mbar_init(uint32_t mbar, uint32_t count) {
    asm volatile("mbarrier.init.shared.b64 [%0], %1;" :: "r"(mbar), "r"(count) : "memory");
}
__device__ __forceinline__ void mbar_expect_tx(uint32_t mbar, uint32_t bytes) {
    asm volatile("mbarrier.arrive.expect_tx.shared.b64 _, [%0], %1;"
                 :: "r"(mbar), "r"(bytes) : "memory");
}
__device__ __forceinline__ void mbar_wait(uint32_t mbar, uint32_t parity) {
    uint32_t done;
    asm volatile("{\n\t.reg .pred p;\n\t"
                 "mbarrier.try_wait.parity.acquire.cta.shared::cta.b64 p, [%1], %2;\n\t"
                 "selp.b32 %0, 1, 0, p;\n\t}"
                 : "=r"(done) : "r"(mbar), "r"(parity) : "memory");
    if (!done) {
        asm volatile("{\n\t.reg .pred P1;\n\t"
                     "WL_%=:\n\t"
                     "mbarrier.try_wait.parity.acquire.cta.shared::cta.b64 P1, [%0], %1, 0x989680;\n\t"
                     "@P1 bra.uni WD_%=;\n\t"
                     "bra.uni WL_%=;\n\t"
                     "WD_%=:\n\t}"
                     :: "r"(mbar), "r"(parity) : "memory");
    }
}

__device__ __forceinline__ void tma_load_tile(const CUtensorMap* tm, uint32_t dst,
                                              uint32_t mbar, uint32_t tile) {
    const int c0 = (int)(tile & 63u) * FW_TW;       // d offset (elements)
    const int r0 = (int)(tile >> 6) * FW_N;         // flattened row offset
#pragma unroll
    for (int q = 0; q < 4; ++q) {
        asm volatile(
            "cp.async.bulk.tensor.2d.shared::cta.global.tile.mbarrier::complete_tx::bytes "
            "[%0], [%1, {%2, %3}], [%4];"
            :: "r"(dst + q * FW_BOX_BYTES), "l"(tm), "r"(c0), "r"(r0 + q * 256), "r"(mbar)
            : "memory");
    }
}

// ---------------- kernel ----------------

__global__ __launch_bounds__(FW_THREADS, 2)
void fwht1024_tma(const __grid_constant__ CUtensorMap tin,
                  float* __restrict__ y) {
    extern __shared__ __align__(1024) unsigned char smem[];
    u64t* bufs = reinterpret_cast<u64t*>(smem);   // float2 units

    uint32_t smem_u32;
    asm("{ .reg .u64 t; cvta.to.shared.u64 t, %1; cvt.u32.u64 %0, t; }"
        : "=r"(smem_u32) : "l"(smem));
    const uint32_t mbar = smem_u32 + FW_MBAR_OFF;

    const int tid = threadIdx.x;
    const int dh  = tid & 3;          // float2 column (0..3) within 8-float tile
    const int jt  = tid >> 2;         // 0..31
    const uint32_t jsw = (uint32_t)(jt & 3);   // phase-B load swizzle

    if (tid == 0) {
#pragma unroll
        for (int s = 0; s < FW_NBUF; ++s) mbar_init(mbar + 8 * s, 1);
    }
    __syncthreads();

    const uint32_t stride = gridDim.x;

    // prologue: prefetch tiles t0 -> slot 0 and t0+stride -> slot 1
    if (tid == 0) {
        if (blockIdx.x < FW_NTILES) {
            mbar_expect_tx(mbar, FW_TILE_BYTES);
            tma_load_tile(&tin, smem_u32, mbar, blockIdx.x);
        }
        if (blockIdx.x + stride < FW_NTILES) {
            mbar_expect_tx(mbar + 8, FW_TILE_BYTES);
            tma_load_tile(&tin, smem_u32 + FW_TILE_BYTES, mbar + 8,
                          blockIdx.x + stride);
        }
    }

    uint32_t phases = 0;   // bit s = parity for next wait on slot s
    uint32_t s = 0;

    for (uint32_t t = blockIdx.x; t < FW_NTILES; t += stride) {
        const uint32_t s1 = (s + 1 >= FW_NBUF) ? s + 1 - FW_NBUF : s + 1;
        const uint32_t s2 = (s + 2 >= FW_NBUF) ? s + 2 - FW_NBUF : s + 2;

        // prefetch tile t+2 into slot s2 — no wait needed: slot s2 was last
        // read by tile t-1's phase-B loads, which all warps passed before
        // t-1's post-load __syncthreads (one full iteration ago).
        const uint32_t t2 = t + 2 * stride;
        if (tid == 0 && t2 < FW_NTILES) {
            mbar_expect_tx(mbar + 8 * s2, FW_TILE_BYTES);
            tma_load_tile(&tin, smem_u32 + s2 * FW_TILE_BYTES, mbar + 8 * s2, t2);
        }

        // wait for current tile data (issued 2 iterations ago)
        mbar_wait(mbar + 8 * s, (phases >> s) & 1u);
        phases ^= 1u << s;

        u64t* buf = bufs + s * (FW_TILE_BYTES / 8);
        u64t v[32];

        // ---- phase A: rows 32a + jt (linear layout: slot = row*4 + dh) ----
#pragma unroll
        for (int a = 0; a < 32; ++a)
            v[a] = buf[128 * a + tid];

#pragma unroll
        for (int h = 1; h < 32; h <<= 1) {
#pragma unroll
            for (int a = 0; a < 32; ++a)
                if ((a & h) == 0) bfly(v[a], v[a | h]);
        }

        // store element (a, b=jt) at slot (a*32 + (jt^(a&3)))*4 + dh
#pragma unroll
        for (int a = 0; a < 32; ++a)
            buf[(a * 32 + (jt ^ (a & 3))) * 4 + dh] = v[a];

        __syncthreads();

        // ---- phase B: element (a=jt, b=i) from (jt*32 + (i^jsw))*4 + dh ----
        const uint32_t pb = (uint32_t)(jt * 128 + dh);
#pragma unroll
        for (int i = 0; i < 32; ++i)
            v[i] = buf[pb + (((uint32_t)i ^ jsw) << 2)];

        // all smem reads of slot s done -> safe for later prefetch overwrite
        __syncthreads();

#pragma unroll
        for (int h = 1; h < 32; h <<= 1) {
#pragma unroll
            for (int i = 0; i < 32; ++i)
                if ((i & h) == 0) bfly(v[i], v[i | h]);
        }

        // ---- output: rows n = jt*32 + i, streaming STG.64 ----
        {
            const uint32_t b  = t >> 6;
            const uint32_t dt = t & 63u;
            float2* __restrict__ yout = reinterpret_cast<float2*>(
                y + (size_t)b * (FW_N * FW_D) + dt * FW_TW + dh * 2);
#pragma unroll
            for (int i = 0; i < 32; ++i) {
                float2 f = *reinterpret_cast<float2*>(&v[i]);
                __stcs(&yout[(size_t)(jt * 32 + i) * (FW_D / 2)], f);
            }
        }

        s = s1;
    }
}

// ---------------- host ----------------

typedef CUresult (*EncodeTiledFn)(
    CUtensorMap*, CUtensorMapDataType, cuuint32_t, void*,
    const cuuint64_t*, const cuuint64_t*, const cuuint32_t*, const cuuint32_t*,
    CUtensorMapInterleave, CUtensorMapSwizzle, CUtensorMapL2promotion,
    CUtensorMapFloatOOBfill);

extern "C" void kernel_launch(void* const* d_in, const int* in_sizes, int n_in,
                              void* d_out, int out_size) {
    void* xp = (void*)d_in[0];
    float* yp = (float*)d_out;

    void* fn = nullptr;
    cudaDriverEntryPointQueryResult qr;
    cudaGetDriverEntryPoint("cuTensorMapEncodeTiled", &fn, cudaEnableDefault, &qr);
    EncodeTiledFn encode = (EncodeTiledFn)fn;

    cuuint64_t dims[2]    = {FW_D, (cuuint64_t)64 * FW_N};  // {512, 65536}
    cuuint64_t strides[1] = {FW_D * 4};                     // 2048 B per row
    cuuint32_t box[2]     = {FW_TW, 256};
    cuuint32_t es[2]      = {1, 1};

    CUtensorMap tin;
    encode(&tin, CU_TENSOR_MAP_DATA_TYPE_FLOAT32, 2, xp, dims, strides, box, es,
           CU_TENSOR_MAP_INTERLEAVE_NONE, CU_TENSOR_MAP_SWIZZLE_NONE,
           CU_TENSOR_MAP_L2_PROMOTION_L2_128B, CU_TENSOR_MAP_FLOAT_OOB_FILL_NONE);

    cudaFuncSetAttribute(fwht1024_tma,
                         cudaFuncAttributeMaxDynamicSharedMemorySize,
                         FW_SMEM_BYTES);

    int sms = 148;
    cudaDeviceGetAttribute(&sms, cudaDevAttrMultiProcessorCount, 0);

    fwht1024_tma<<<sms * 2, FW_THREADS, FW_SMEM_BYTES>>>(tin, yp);
}

// round 14
// speedup vs baseline: 1.0884x; 1.0884x over previous
#include <cuda_runtime.h>
#include <cuda.h>
#include <cstdint>

// FWHT n=1024 over x[64,1024,512] f32, single pass, TMA-pipelined.
//
// R14 = R12 memory structure exactly (16-float-wide tiles, 3 x 64KB
// buffers, persistent 1 CTA/SM, depth-2 TMA prefetch, STG.cs output,
// 64B global segments) but 512 threads (16 warps, 4/SMSP), one float
// per thread: doubles independent warp streams per scheduler to hide
// LDS latency + butterfly dependency chains.
//
// n = 32*a + b. Phase A: FWHT_32 over a (rows 32a+jt); swizzled smem
// exchange; Phase B: FWHT_32 over b (rows jt*32+b) -> STG.

#define FW_N 1024
#define FW_D 512
#define FW_TW 16                          // tile width in floats (64 B)
#define FW_THREADS 512
#define FW_NTILES (64 * (FW_D / FW_TW))   // 2048
#define FW_TILE_BYTES (FW_N * FW_TW * 4)  // 65536
#define FW_NBUF 3
#define FW_MBAR_OFF (FW_NBUF * FW_TILE_BYTES)
#define FW_SMEM_BYTES (FW_MBAR_OFF + 64)

__device__ __forceinline__ void mbar_init(uint32_t mbar, uint32_t count) {
    asm volatile("mbarrier.init.shared.b64 [%0], %1;" :: "r"(mbar), "r"(count) : "memory");
}
__device__ __forceinline__ void mbar_expect_tx(uint32_t mbar, uint32_t bytes) {
    asm volatile("mbarrier.arrive.expect_tx.shared.b64 _, [%0], %1;"
                 :: "r"(mbar), "r"(bytes) : "memory");
}
__device__ __forceinline__ void mbar_wait(uint32_t mbar, uint32_t parity) {
    uint32_t done;
    asm volatile("{\n\t.reg .pred p;\n\t"
                 "mbarrier.try_wait.parity.acquire.cta.shared::cta.b64 p, [%1], %2;\n\t"
                 "selp.b32 %0, 1, 0, p;\n\t}"
                 : "=r"(done) : "r"(mbar), "r"(parity) : "memory");
    if (!done) {
        asm volatile("{\n\t.reg .pred P1;\n\t"
                     "WL_%=:\n\t"
                     "mbarrier.try_wait.parity.acquire.cta.shared::cta.b64 P1, [%0], %1, 0x989680;\n\t"
                     "@P1 bra.uni WD_%=;\n\t"
                     "bra.uni WL_%=;\n\t"
                     "WD_%=:\n\t}"
                     :: "r"(mbar), "r"(parity) : "memory");
    }
}

__device__ __forceinline__ void tma_load_tile(const CUtensorMap* tm, uint32_t dst,
                                              uint32_t mbar, uint32_t tile) {
    const int c0 = (int)(tile & 31u) * FW_TW;       // d offset (elements)
    const int r0 = (int)(tile >> 5) * FW_N;         // flattened row offset
#pragma unroll
    for (int q = 0; q < 4; ++q) {
        asm volatile(
            "cp.async.bulk.tensor.2d.shared::cta.global.tile.mbarrier::complete_tx::bytes "
            "[%0], [%1, {%2, %3}], [%4];"
            :: "r"(dst + q * 16384), "l"(tm), "r"(c0), "r"(r0 + q * 256), "r"(mbar)
            : "memory");
    }
}

// ---------------- kernel ----------------

__global__ __launch_bounds__(FW_THREADS, 1)
void fwht1024_tma(const __grid_constant__ CUtensorMap tin,
                  float* __restrict__ y) {
    extern __shared__ __align__(1024) unsigned char smem[];
    float* bufs = reinterpret_cast<float*>(smem);   // float units

    uint32_t smem_u32;
    asm("{ .reg .u64 t; cvta.to.shared.u64 t, %1; cvt.u32.u64 %0, t; }"
        : "=r"(smem_u32) : "l"(smem));
    const uint32_t mbar = smem_u32 + FW_MBAR_OFF;

    const int tid = threadIdx.x;
    const int df  = tid & 15;         // float column (0..15) of the 16-float tile
    const int jt  = tid >> 4;         // 0..31
    const uint32_t jsw = (uint32_t)(jt & 1);   // phase-B load parity swizzle

    if (tid == 0) {
#pragma unroll
        for (int s = 0; s < FW_NBUF; ++s) mbar_init(mbar + 8 * s, 1);
    }
    __syncthreads();

    const uint32_t stride = gridDim.x;

    // prologue: prefetch tiles t0 -> slot 0 and t0+stride -> slot 1
    if (tid == 0) {
        if (blockIdx.x < FW_NTILES) {
            mbar_expect_tx(mbar, FW_TILE_BYTES);
            tma_load_tile(&tin, smem_u32, mbar, blockIdx.x);
        }
        if (blockIdx.x + stride < FW_NTILES) {
            mbar_expect_tx(mbar + 8, FW_TILE_BYTES);
            tma_load_tile(&tin, smem_u32 + FW_TILE_BYTES, mbar + 8,
                          blockIdx.x + stride);
        }
    }

    uint32_t phases = 0;   // bit s = parity for next wait on slot s
    uint32_t s = 0;

    for (uint32_t t = blockIdx.x; t < FW_NTILES; t += stride) {
        const uint32_t s1 = (s + 1 >= FW_NBUF) ? s + 1 - FW_NBUF : s + 1;
        const uint32_t s2 = (s + 2 >= FW_NBUF) ? s + 2 - FW_NBUF : s + 2;

        // prefetch tile t+2 into slot s2 — no wait needed: slot s2 was last
        // read by tile t-1's phase-B loads, which all warps passed before
        // t-1's post-load __syncthreads (one full iteration ago).
        const uint32_t t2 = t + 2 * stride;
        if (tid == 0 && t2 < FW_NTILES) {
            mbar_expect_tx(mbar + 8 * s2, FW_TILE_BYTES);
            tma_load_tile(&tin, smem_u32 + s2 * FW_TILE_BYTES, mbar + 8 * s2, t2);
        }

        // wait for current tile data (issued 2 iterations ago)
        mbar_wait(mbar + 8 * s, (phases >> s) & 1u);
        phases ^= 1u << s;

        float* buf = bufs + s * (FW_TILE_BYTES / 4);
        float v[32];

        // ---- phase A: rows 32a + jt (linear: slot = row*16 + df) ----
#pragma unroll
        for (int a = 0; a < 32; ++a)
            v[a] = buf[512 * a + tid];

#pragma unroll
        for (int h = 1; h < 32; h <<= 1) {
#pragma unroll
            for (int a = 0; a < 32; ++a) {
                if ((a & h) == 0) {
                    const float p = v[a], q = v[a | h];
                    v[a]     = p + q;
                    v[a | h] = p - q;
                }
            }
        }

        // store element (a, b=jt) at slot (a*32 + (jt^(a&1)))*16 + df
#pragma unroll
        for (int a = 0; a < 32; ++a)
            buf[(a * 32 + (jt ^ (a & 1))) * 16 + df] = v[a];

        __syncthreads();

        // ---- phase B: element (a=jt, b=i) from (jt*32 + (i^jsw))*16 + df ----
        const uint32_t pb = (uint32_t)(jt * 512 + df);
#pragma unroll
        for (int i = 0; i < 32; ++i)
            v[i] = buf[pb + (((uint32_t)i ^ jsw) << 4)];

        // all smem reads of slot s done -> safe for later prefetch overwrite
        __syncthreads();

#pragma unroll
        for (int h = 1; h < 32; h <<= 1) {
#pragma unroll
            for (int i = 0; i < 32; ++i) {
                if ((i & h) == 0) {
                    const float p = v[i], q = v[i | h];
                    v[i]     = p + q;
                    v[i | h] = p - q;
                }
            }
        }

        // ---- output: rows n = jt*32 + i, streaming STG (64B per 16 lanes) --
        {
            const uint32_t b  = t >> 5;
            const uint32_t dt = t & 31u;
            float* __restrict__ yout =
                y + (size_t)b * (FW_N * FW_D) + dt * FW_TW + df;
#pragma unroll
            for (int i = 0; i < 32; ++i)
                __stcs(&yout[(size_t)(jt * 32 + i) * FW_D], v[i]);
        }

        s = s1;
    }
}

// ---------------- host ----------------

typedef CUresult (*EncodeTiledFn)(
    CUtensorMap*, CUtensorMapDataType, cuuint32_t, void*,
    const cuuint64_t*, const cuuint64_t*, const cuuint32_t*, const cuuint32_t*,
    CUtensorMapInterleave, CUtensorMapSwizzle, CUtensorMapL2promotion,
    CUtensorMapFloatOOBfill);

extern "C" void kernel_launch(void* const* d_in, const int* in_sizes, int n_in,
                              void* d_out, int out_size) {
    void* xp = (void*)d_in[0];
    float* yp = (float*)d_out;

    void* fn = nullptr;
    cudaDriverEntryPointQueryResult qr;
    cudaGetDriverEntryPoint("cuTensorMapEncodeTiled", &fn, cudaEnableDefault, &qr);
    EncodeTiledFn encode = (EncodeTiledFn)fn;

    cuuint64_t dims[2]    = {FW_D, (cuuint64_t)64 * FW_N};  // {512, 65536}
    cuuint64_t strides[1] = {FW_D * 4};                     // 2048 B per row
    cuuint32_t box[2]     = {FW_TW, 256};
    cuuint32_t es[2]      = {1, 1};

    CUtensorMap tin;
    encode(&tin, CU_TENSOR_MAP_DATA_TYPE_FLOAT32, 2, xp, dims, strides, box, es,
           CU_TENSOR_MAP_INTERLEAVE_NONE, CU_TENSOR_MAP_SWIZZLE_NONE,
           CU_TENSOR_MAP_L2_PROMOTION_L2_128B, CU_TENSOR_MAP_FLOAT_OOB_FILL_NONE);

    cudaFuncSetAttribute(fwht1024_tma,
                         cudaFuncAttributeMaxDynamicSharedMemorySize,
                         FW_SMEM_BYTES);

    int sms = 148;
    cudaDeviceGetAttribute(&sms, cudaDevAttrMultiProcessorCount, 0);

    fwht1024_tma<<<sms, FW_THREADS, FW_SMEM_BYTES>>>(tin, yp);
}

// round 15
// speedup vs baseline: 1.1371x; 1.0448x over previous
#include <cuda_runtime.h>
#include <cuda.h>
#include <cstdint>

// FWHT n=1024 over x[64,1024,512] f32, single pass, TMA-pipelined.
//
// R15 = R12 (256 threads, 3 x 64KB buffers, persistent 1 CTA/SM, depth-2
// TMA prefetch, register FWHT, STG.cs output) + DYNAMIC tile assignment:
// tiles are claimed via a global atomic counter instead of grid-stride,
// removing the static 13/14-tiles-per-CTA imbalance and the between-SM
// speed-spread tail (slow SMs claim fewer tiles). Counter is reset by a
// graph-capturable cudaMemsetAsync before each launch.
//
// n = 32*a + b. Phase A: FWHT_32 over a (rows 32a+jt); swizzled smem
// exchange; Phase B: FWHT_32 over b (rows jt*32+b) -> STG.

#define FW_N 1024
#define FW_D 512
#define FW_TW 16                          // tile width in floats (64 B)
#define FW_THREADS 256
#define FW_NTILES (64 * (FW_D / FW_TW))   // 2048
#define FW_TILE_BYTES (FW_N * FW_TW * 4)  // 65536
#define FW_NBUF 3
#define FW_MBAR_OFF (FW_NBUF * FW_TILE_BYTES)
#define FW_SMEM_BYTES (FW_MBAR_OFF + 64)

typedef unsigned long long u64t;

__device__ unsigned int g_tile_ctr;       // reset to 0 before every launch

// packed butterfly on a float2-as-u64: (a,b) -> (a+b, a-b)
__device__ __forceinline__ void bfly(u64t& a, u64t& b) {
    u64t s, d;
    asm("add.rn.f32x2 %0, %2, %3;\n\t"
        "sub.rn.f32x2 %1, %2, %3;"
        : "=l"(s), "=l"(d)
        : "l"(a), "l"(b));
    a = s; b = d;
}

__device__ __forceinline__ void mbar_init(uint32_t mbar, uint32_t count) {
    asm volatile("mbarrier.init.shared.b64 [%0], %1;" :: "r"(mbar), "r"(count) : "memory");
}
__device__ __forceinline__ void mbar_expect_tx(uint32_t mbar, uint32_t bytes) {
    asm volatile("mbarrier.arrive.expect_tx.shared.b64 _, [%0], %1;"
                 :: "r"(mbar), "r"(bytes) : "memory");
}
__device__ __forceinline__ void mbar_wait(uint32_t mbar, uint32_t parity) {
    uint32_t done;
    asm volatile("{\n\t.reg .pred p;\n\t"
                 "mbarrier.try_wait.parity.acquire.cta.shared::cta.b64 p, [%1], %2;\n\t"
                 "selp.b32 %0, 1, 0, p;\n\t}"
                 : "=r"(done) : "r"(mbar), "r"(parity) : "memory");
    if (!done) {
        asm volatile("{\n\t.reg .pred P1;\n\t"
                     "WL_%=:\n\t"
                     "mbarrier.try_wait.parity.acquire.cta.shared::cta.b64 P1, [%0], %1, 0x989680;\n\t"
                     "@P1 bra.uni WD_%=;\n\t"
                     "bra.uni WL_%=;\n\t"
                     "WD_%=:\n\t}"
                     :: "r"(mbar), "r"(parity) : "memory");
    }
}

__device__ __forceinline__ void tma_load_tile(const CUtensorMap* tm, uint32_t dst,
                                              uint32_t mbar, uint32_t tile) {
    const int c0 = (int)(tile & 31u) * FW_TW;       // d offset (elements)
    const int r0 = (int)(tile >> 5) * FW_N;         // flattened row offset
#pragma unroll
    for (int q = 0; q < 4; ++q) {
        asm volatile(
            "cp.async.bulk.tensor.2d.shared::cta.global.tile.mbarrier::complete_tx::bytes "
            "[%0], [%1, {%2, %3}], [%4];"
            :: "r"(dst + q * 16384), "l"(tm), "r"(c0), "r"(r0 + q * 256), "r"(mbar)
            : "memory");
    }
}

// ---------------- kernel ----------------

__global__ __launch_bounds__(FW_THREADS, 1)
void fwht1024_tma(const __grid_constant__ CUtensorMap tin,
                  float* __restrict__ y) {
    extern __shared__ __align__(1024) unsigned char smem[];
    u64t* bufs = reinterpret_cast<u64t*>(smem);   // float2 units

    uint32_t smem_u32;
    asm("{ .reg .u64 t; cvta.to.shared.u64 t, %1; cvt.u32.u64 %0, t; }"
        : "=r"(smem_u32) : "l"(smem));
    const uint32_t mbar = smem_u32 + FW_MBAR_OFF;
    // per-slot claimed-tile broadcast words (after the 3 mbarriers)
    volatile uint32_t* smem_q =
        reinterpret_cast<volatile uint32_t*>(smem + FW_MBAR_OFF + 32);

    const int tid = threadIdx.x;
    const int dh  = tid & 7;          // float2 column (0..7) within 16-float tile
    const int jt  = tid >> 3;         // 0..31
    const uint32_t jsw = (uint32_t)(jt & 1);   // phase-B load swizzle

    // prologue: init mbarriers, claim first two tiles, start their loads
    if (tid == 0) {
#pragma unroll
        for (int s = 0; s < FW_NBUF; ++s) mbar_init(mbar + 8 * s, 1);
        const uint32_t q0 = atomicAdd(&g_tile_ctr, 1u);
        const uint32_t q1 = atomicAdd(&g_tile_ctr, 1u);
        smem_q[0] = q0;
        smem_q[1] = q1;
        if (q0 < FW_NTILES) {
            mbar_expect_tx(mbar, FW_TILE_BYTES);
            tma_load_tile(&tin, smem_u32, mbar, q0);
        }
        if (q1 < FW_NTILES) {
            mbar_expect_tx(mbar + 8, FW_TILE_BYTES);
            tma_load_tile(&tin, smem_u32 + FW_TILE_BYTES, mbar + 8, q1);
        }
    }
    __syncthreads();

    uint32_t qloc[FW_NBUF];
    qloc[0] = smem_q[0];
    qloc[1] = smem_q[1];
    qloc[2] = FW_NTILES;   // placeholder; set before first use (iter 1)

    uint32_t phases = 0;   // bit s = parity for next wait on slot s
    uint32_t s = 0;

    while (qloc[s] < FW_NTILES) {
        const uint32_t s1 = (s + 1 >= FW_NBUF) ? s + 1 - FW_NBUF : s + 1;
        const uint32_t s2 = (s + 2 >= FW_NBUF) ? s + 2 - FW_NBUF : s + 2;

        // claim + prefetch a new tile into slot s2 — no wait needed: slot s2
        // was last read by the phase-B loads two iterations ago, behind a
        // __syncthreads all threads (incl. tid 0) have passed.
        if (tid == 0) {
            const uint32_t q2 = atomicAdd(&g_tile_ctr, 1u);
            smem_q[s2] = q2;
            if (q2 < FW_NTILES) {
                mbar_expect_tx(mbar + 8 * s2, FW_TILE_BYTES);
                tma_load_tile(&tin, smem_u32 + s2 * FW_TILE_BYTES, mbar + 8 * s2, q2);
            }
        }

        // wait for current tile data (issued 2 iterations ago)
        mbar_wait(mbar + 8 * s, (phases >> s) & 1u);
        phases ^= 1u << s;

        const uint32_t t = qloc[s];
        u64t* buf = bufs + s * (FW_TILE_BYTES / 8);
        u64t v[32];

        // ---- phase A: rows 32a + jt, a = 0..31 (linear layout from TMA) ----
#pragma unroll
        for (int a = 0; a < 32; ++a)
            v[a] = buf[256 * a + tid];

#pragma unroll
        for (int h = 1; h < 32; h <<= 1) {
#pragma unroll
            for (int a = 0; a < 32; ++a)
                if ((a & h) == 0) bfly(v[a], v[a | h]);
        }

        // store element (a, b=jt) at swizzled slot (a*32 + (jt^(a&1)))*8 + dh
#pragma unroll
        for (int a = 0; a < 32; ++a)
            buf[(a * 32 + (jt ^ (a & 1))) * 8 + dh] = v[a];

        __syncthreads();

        // tid 0's smem_q[s2] write is now visible to all threads
        qloc[s2] = smem_q[s2];

        // ---- phase B: element (a=jt, b=i) from slot (jt*32 + (i^jsw))*8+dh ----
        const uint32_t pb = (uint32_t)(jt * 256 + dh);
#pragma unroll
        for (int i = 0; i < 32; ++i)
            v[i] = buf[pb + (((uint32_t)i ^ jsw) << 3)];

        // all smem reads of slot s done -> safe for later prefetch overwrite
        __syncthreads();

#pragma unroll
        for (int h = 1; h < 32; h <<= 1) {
#pragma unroll
            for (int i = 0; i < 32; ++i)
                if ((i & h) == 0) bfly(v[i], v[i | h]);
        }

        // ---- output: rows n = jt*32 + i, streaming STG.64 (64B/4-lane group)
        {
            const uint32_t b  = t >> 5;
            const uint32_t dt = t & 31u;
            float2* __restrict__ yout = reinterpret_cast<float2*>(
                y + (size_t)b * (FW_N * FW_D) + dt * FW_TW + dh * 2);
#pragma unroll
            for (int i = 0; i < 32; ++i) {
                float2 f = *reinterpret_cast<float2*>(&v[i]);
                __stcs(&yout[(size_t)(jt * 32 + i) * (FW_D / 2)], f);
            }
        }

        s = s1;
    }
}

// ---------------- host ----------------

typedef CUresult (*EncodeTiledFn)(
    CUtensorMap*, CUtensorMapDataType, cuuint32_t, void*,
    const cuuint64_t*, const cuuint64_t*, const cuuint32_t*, const cuuint32_t*,
    CUtensorMapInterleave, CUtensorMapSwizzle, CUtensorMapL2promotion,
    CUtensorMapFloatOOBfill);

extern "C" void kernel_launch(void* const* d_in, const int* in_sizes, int n_in,
                              void* d_out, int out_size) {
    void* xp = (void*)d_in[0];
    float* yp = (float*)d_out;

    void* fn = nullptr;
    cudaDriverEntryPointQueryResult qr;
    cudaGetDriverEntryPoint("cuTensorMapEncodeTiled", &fn, cudaEnableDefault, &qr);
    EncodeTiledFn encode = (EncodeTiledFn)fn;

    cuuint64_t dims[2]    = {FW_D, (cuuint64_t)64 * FW_N};  // {512, 65536}
    cuuint64_t strides[1] = {FW_D * 4};                     // 2048 B per row
    cuuint32_t box[2]     = {FW_TW, 256};
    cuuint32_t es[2]      = {1, 1};

    CUtensorMap tin;
    encode(&tin, CU_TENSOR_MAP_DATA_TYPE_FLOAT32, 2, xp, dims, strides, box, es,
           CU_TENSOR_MAP_INTERLEAVE_NONE, CU_TENSOR_MAP_SWIZZLE_NONE,
           CU_TENSOR_MAP_L2_PROMOTION_L2_128B, CU_TENSOR_MAP_FLOAT_OOB_FILL_NONE);

    cudaFuncSetAttribute(fwht1024_tma,
                         cudaFuncAttributeMaxDynamicSharedMemorySize,
                         FW_SMEM_BYTES);

    // reset the dynamic tile counter (async memset: graph-capturable)
    void* ctr_addr = nullptr;
    cudaGetSymbolAddress(&ctr_addr, g_tile_ctr);
    cudaMemsetAsync(ctr_addr, 0, sizeof(unsigned int));

    int sms = 148;
    cudaDeviceGetAttribute(&sms, cudaDevAttrMultiProcessorCount, 0);

    fwht1024_tma<<<sms, FW_THREADS, FW_SMEM_BYTES>>>(tin, yp);
}